// round 1
// baseline (speedup 1.0000x reference)
#include <cuda_runtime.h>

#define C      128
#define CH     64          // c/2
#define KNB    16
#define PB     4           // points per warp
#define WARPS  8
#define THREADS 256
#define NPTS   (8*4096)

// Scratch (device globals — no allocation allowed in kernel_launch)
__device__ float g_B[C*C];     // B[i][j]  = sum_o wq[o][i] * wk[o][j]
__device__ float g_wvT[C*C];   // wvT[i][o] = wv[o][i]

__global__ void precompute_kernel(const float* __restrict__ wq,
                                  const float* __restrict__ wk,
                                  const float* __restrict__ wv) {
    const int i = blockIdx.x;   // 0..127
    const int j = threadIdx.x;  // 0..127
    float acc = 0.f;
#pragma unroll
    for (int o = 0; o < CH; ++o)
        acc = fmaf(wq[o*C + i], wk[o*C + j], acc);
    g_B[i*C + j]   = acc;
    g_wvT[i*C + j] = wv[j*C + i];
}

__global__ void __launch_bounds__(THREADS, 2)
attn_kernel(const float* __restrict__ fc,   // [NPTS][C]      fea_center
            const float* __restrict__ fn,   // [NPTS][KNB][C] fea_near
            float* __restrict__ out)        // [NPTS][C]
{
    __shared__ float sh_xc[WARPS][PB*C];
    __shared__ float sh_u [WARPS][PB*C];
    __shared__ float sh_y [WARPS][PB*C];

    const int warp = threadIdx.x >> 5;
    const int lane = threadIdx.x & 31;
    const int p0   = (blockIdx.x * WARPS + warp) * PB;
    if (p0 >= NPTS) return;

    float* xc = sh_xc[warp];
    float* us = sh_u [warp];
    float* ys = sh_y [warp];
    const int l4 = lane * 4;

    // ---- stage center features ----
#pragma unroll
    for (int p = 0; p < PB; ++p)
        *(float4*)(xc + p*C + l4) =
            *(const float4*)(fc + (size_t)(p0 + p)*C + l4);
    __syncwarp();

    // ---- Phase A: u[p][j] = sum_i B[i][j] * xc[p][i] (lane owns j = l4..l4+3) ----
    {
        float4 u4[PB];
#pragma unroll
        for (int p = 0; p < PB; ++p) u4[p] = make_float4(0.f, 0.f, 0.f, 0.f);
#pragma unroll 2
        for (int i0 = 0; i0 < C; i0 += 4) {
            float4 c4[PB];
#pragma unroll
            for (int p = 0; p < PB; ++p)
                c4[p] = *(const float4*)(xc + p*C + i0);   // broadcast
#pragma unroll
            for (int di = 0; di < 4; ++di) {
                const float4 b4 = *(const float4*)(g_B + (i0 + di)*C + l4);
#pragma unroll
                for (int p = 0; p < PB; ++p) {
                    const float cv = (&c4[p].x)[di];
                    u4[p].x = fmaf(b4.x, cv, u4[p].x);
                    u4[p].y = fmaf(b4.y, cv, u4[p].y);
                    u4[p].z = fmaf(b4.z, cv, u4[p].z);
                    u4[p].w = fmaf(b4.w, cv, u4[p].w);
                }
            }
        }
#pragma unroll
        for (int p = 0; p < PB; ++p)
            *(float4*)(us + p*C + l4) = u4[p];
    }
    __syncwarp();

    // ---- Middle: logits -> softmax -> y = sum_j w_j * x_j ----
#pragma unroll 1
    for (int p = 0; p < PB; ++p) {
        const float* xn = fn + (size_t)(p0 + p)*(KNB*C);
        float4 x[KNB];
#pragma unroll
        for (int j = 0; j < KNB; ++j)
            x[j] = *(const float4*)(xn + j*C + l4);

        const float4 u4 = *(const float4*)(us + p*C + l4);
        const float4 c4 = *(const float4*)(xc + p*C + l4);

        float lg[KNB + 1];
#pragma unroll
        for (int j = 0; j < KNB; ++j) {
            float t = u4.x * x[j].x;
            t = fmaf(u4.y, x[j].y, t);
            t = fmaf(u4.z, x[j].z, t);
            t = fmaf(u4.w, x[j].w, t);
            lg[j] = t;
        }
        {
            float t = u4.x * c4.x;
            t = fmaf(u4.y, c4.y, t);
            t = fmaf(u4.z, c4.z, t);
            t = fmaf(u4.w, c4.w, t);
            lg[KNB] = t;
        }

        // butterfly all-reduce: every lane ends with full dot products
        for (int off = 16; off; off >>= 1) {
#pragma unroll
            for (int t = 0; t <= KNB; ++t)
                lg[t] += __shfl_xor_sync(0xffffffffu, lg[t], off);
        }

        // softmax over 17 logits (scale 1/sqrt(64) = 0.125, max-stabilized)
        float m = lg[0];
#pragma unroll
        for (int t = 1; t <= KNB; ++t) m = fmaxf(m, lg[t]);
        float s = 0.f;
#pragma unroll
        for (int t = 0; t <= KNB; ++t) {
            lg[t] = __expf((lg[t] - m) * 0.125f);
            s += lg[t];
        }
        const float rs = 1.f / s;

        float4 y4;
        y4.x = lg[KNB] * c4.x;
        y4.y = lg[KNB] * c4.y;
        y4.z = lg[KNB] * c4.z;
        y4.w = lg[KNB] * c4.w;
#pragma unroll
        for (int j = 0; j < KNB; ++j) {
            y4.x = fmaf(lg[j], x[j].x, y4.x);
            y4.y = fmaf(lg[j], x[j].y, y4.y);
            y4.z = fmaf(lg[j], x[j].z, y4.z);
            y4.w = fmaf(lg[j], x[j].w, y4.w);
        }
        y4.x *= rs; y4.y *= rs; y4.z *= rs; y4.w *= rs;
        *(float4*)(ys + p*C + l4) = y4;
    }
    __syncwarp();

    // ---- Phase C: out[p][o] = sum_i wvT[i][o] * y[p][i] (lane owns o = l4..l4+3) ----
    {
        float4 o4[PB];
#pragma unroll
        for (int p = 0; p < PB; ++p) o4[p] = make_float4(0.f, 0.f, 0.f, 0.f);
#pragma unroll 2
        for (int i0 = 0; i0 < C; i0 += 4) {
            float4 y4[PB];
#pragma unroll
            for (int p = 0; p < PB; ++p)
                y4[p] = *(const float4*)(ys + p*C + i0);   // broadcast
#pragma unroll
            for (int di = 0; di < 4; ++di) {
                const float4 w4 = *(const float4*)(g_wvT + (i0 + di)*C + l4);
#pragma unroll
                for (int p = 0; p < PB; ++p) {
                    const float yv = (&y4[p].x)[di];
                    o4[p].x = fmaf(w4.x, yv, o4[p].x);
                    o4[p].y = fmaf(w4.y, yv, o4[p].y);
                    o4[p].z = fmaf(w4.z, yv, o4[p].z);
                    o4[p].w = fmaf(w4.w, yv, o4[p].w);
                }
            }
        }
#pragma unroll
        for (int p = 0; p < PB; ++p)
            *(float4*)(out + (size_t)(p0 + p)*C + l4) = o4[p];
    }
}

extern "C" void kernel_launch(void* const* d_in, const int* in_sizes, int n_in,
                              void* d_out, int out_size) {
    const float* fc = (const float*)d_in[0];   // fea_center [8,4096,1,128]
    const float* fn = (const float*)d_in[1];   // fea_near   [8,4096,16,128]
    const float* wq = (const float*)d_in[2];   // [64,128]
    const float* wk = (const float*)d_in[3];   // [64,128]
    const float* wv = (const float*)d_in[4];   // [128,128]
    float* out = (float*)d_out;                // [8,4096,128]

    precompute_kernel<<<C, C>>>(wq, wk, wv);
    attn_kernel<<<NPTS/(PB*WARPS), THREADS>>>(fc, fn, out);
}